// round 8
// baseline (speedup 1.0000x reference)
#include <cuda_runtime.h>

#define PH 7
#define PW 7
#define ROI_SCALE 0.0625f

#define C_DIM 128
#define H_DIM 50
#define W_DIM 50
#define PLANE (H_DIM * W_DIM)

// Bit-exact vs the as-executed JAX reference: x/7 is computed as
// x * fl(1/7), fl(1/7) = 0x3E124925 (rounds up). DO NOT change.
#define RECIP7_BITS 0x3E124925u

struct __align__(16) RoiTab {
    int   base;          // b * C_DIM * PLANE
    short hs[7], he[7];  // clipped row bounds per ph
    short ws[7], we[7];  // clipped col bounds per pw
    // 4 + 56 = 60 bytes
    int   pad;           // -> 64 bytes
};

__device__ RoiTab g_roi_tab[256];

__global__ void roi_precompute_kernel(const float* __restrict__ rois, int K) {
    int k = blockIdx.x * blockDim.x + threadIdx.x;
    if (k >= K) return;

    const float* r = rois + k * 5;
    int b  = (int)r[0];
    // jnp.round = round-half-even; x * 2^-4 is an exact fp32 multiply
    int x1 = (int)rintf(__fmul_rn(r[1], ROI_SCALE));
    int y1 = (int)rintf(__fmul_rn(r[2], ROI_SCALE));
    int x2 = (int)rintf(__fmul_rn(r[3], ROI_SCALE));
    int y2 = (int)rintf(__fmul_rn(r[4], ROI_SCALE));

    float roi_w = (float)max(x2 - x1 + 1, 1);
    float roi_h = (float)max(y2 - y1 + 1, 1);

    const float recip7 = __uint_as_float(RECIP7_BITS);
    float bin_w = __fmul_rn(roi_w, recip7);
    float bin_h = __fmul_rn(roi_h, recip7);

    RoiTab t;
    t.base = b * C_DIM * PLANE;
    t.pad = 0;
#pragma unroll
    for (int j = 0; j < 7; ++j) {
        float jf = (float)j;
        t.hs[j] = (short)min(max((int)floorf(__fmul_rn(jf, bin_h)) + y1, 0), H_DIM);
        t.he[j] = (short)min(max((int)ceilf(__fmul_rn(jf + 1.0f, bin_h)) + y1, 0), H_DIM);
        t.ws[j] = (short)min(max((int)floorf(__fmul_rn(jf, bin_w)) + x1, 0), W_DIM);
        t.we[j] = (short)min(max((int)ceilf(__fmul_rn(jf + 1.0f, bin_w)) + x1, 0), W_DIM);
    }
    g_roi_tab[k] = t;
}

__global__ void roi_pool_kernel(const float* __restrict__ feat,
                                float* __restrict__ out,
                                int total) {
    unsigned idx = blockIdx.x * blockDim.x + threadIdx.x;
    if (idx >= (unsigned)total) return;

    unsigned pw = idx % PW;
    unsigned ph = (idx / PW) % PH;
    unsigned c  = (idx / (PW * PH)) % C_DIM;
    unsigned k  = idx / (PW * PH * C_DIM);

    const RoiTab* __restrict__ t = &g_roi_tab[k];
    int hstart = t->hs[ph];
    int hend   = t->he[ph];
    int wstart = t->ws[pw];
    int wend   = t->we[pw];

    float m = -1e30f;
    const float* plane = feat + t->base + (int)c * PLANE;
    for (int h = hstart; h < hend; ++h) {
        const float* row = plane + h * W_DIM;
        for (int w = wstart; w < wend; ++w) {
            m = fmaxf(m, row[w]);
        }
    }

    bool empty = (hend <= hstart) || (wend <= wstart);
    out[idx] = empty ? 0.0f : m;
}

extern "C" void kernel_launch(void* const* d_in, const int* in_sizes, int n_in,
                              void* d_out, int out_size) {
    const float* feat = (const float*)d_in[0];
    const float* rois = (const float*)d_in[1];
    float* out = (float*)d_out;

    int K = in_sizes[1] / 5;               // 256
    int total = K * C_DIM * PH * PW;       // 1,605,632

    roi_precompute_kernel<<<1, 256>>>(rois, K);

    int block = 256;
    int grid = (total + block - 1) / block;
    roi_pool_kernel<<<grid, block>>>(feat, out, total);
}